// round 17
// baseline (speedup 1.0000x reference)
#include <cuda_runtime.h>
#include <cuda_fp16.h>
#include <cstdint>

// ---------------------------------------------------------------------------
// FlexibleWaveConv2d, round 17 — fused GEMM+IDWT, all 4 subbands per block.
//   K1 k_dwt  : x -> A2[s][pos][k2][b] half2 (channel pairs packed)
//   K2 k_wprep: w_s -> W2[s][uv][k2][o] half2 (k-pairs, scaled by 2^12)
//   K3 k_fused: block = (xr, y-pair). All 4 subbands resident (s unrolled,
//               acc[4][2][2][4] in regs). Barrier-free LDG tap stream +
//               HFMA2 interp + mma m16n8k16. Epilogue: register-only
//               2-level IDWT -> direct out stores. No g_C, no idwt kernel.
// ---------------------------------------------------------------------------

#define N_A2 (4L*1024*64*32)
#define N_W2 (4L*256*64*128)

static __device__ __half2 g_A2[N_A2];  // [s][pos][k2][b]
static __device__ __half2 g_W2[N_W2];  // [s][u*16+v][k2][o], x 4096

// ---------------------------------------------------------------------------
// K1: 4x4 block Haar, 2 channels per block, half2-packed output.
// ---------------------------------------------------------------------------
__global__ __launch_bounds__(1024) void k_dwt(const float* __restrict__ x) {
    const int xr = blockIdx.x, cp = blockIdx.y;
    __shared__ float vals[2][4][32][33];
    const int tid = threadIdx.x;
    const int b = tid >> 5, y = tid & 31;

#pragma unroll
    for (int ph = 0; ph < 2; ph++) {
        const int ci = 2 * cp + ph;
        const float4* px = reinterpret_cast<const float4*>(x)
                         + ((long)(b * 128 + ci) * 128 + 4 * xr) * 32 + y;
        float4 r0 = px[0], r1 = px[32], r2 = px[64], r3 = px[96];
        float q00 = r0.x + r0.y + r1.x + r1.y;
        float q01 = r0.z + r0.w + r1.z + r1.w;
        float q10 = r2.x + r2.y + r3.x + r3.y;
        float q11 = r2.z + r2.w + r3.z + r3.w;
        vals[ph][0][y][b] = 0.25f * (q00 + q01 + q10 + q11);
        vals[ph][1][y][b] = 0.25f * (q00 - q01 + q10 - q11);
        vals[ph][2][y][b] = 0.25f * (q00 + q01 - q10 - q11);
        vals[ph][3][y][b] = 0.25f * (q00 - q01 - q10 + q11);
    }
    __syncthreads();
    const int y2 = tid >> 5, b2 = tid & 31;
#pragma unroll
    for (int s = 0; s < 4; s++) {
        g_A2[(((long)s * 1024 + xr * 32 + y2) * 64 + cp) * 32 + b2] =
            __floats2half2_rn(vals[0][s][y2][b2], vals[1][s][y2][b2]);
    }
}

// ---------------------------------------------------------------------------
// K2: weight transpose (i,o,u,v) -> [s][uv][k2][o] half2, scaled by 4096.
// ---------------------------------------------------------------------------
__global__ __launch_bounds__(256) void k_wprep(const float* __restrict__ w0,
                                               const float* __restrict__ w1,
                                               const float* __restrict__ w2,
                                               const float* __restrict__ w3) {
    const int k2 = blockIdx.x, s = blockIdx.y;
    const float* w = (s == 0) ? w0 : (s == 1) ? w1 : (s == 2) ? w2 : w3;
    __shared__ float t[2][16][260];
    const int tid = threadIdx.x;

    for (int oc = 0; oc < 8; oc++) {
        for (int idx = tid; idx < 2048; idx += 256) {
            const int kk = idx >> 10, r = idx & 1023;
            const int o = r >> 6, uv4 = (r & 63) << 2;
            const float4 v = *reinterpret_cast<const float4*>(
                &w[((long)(2 * k2 + kk) * 128 + oc * 16 + o) * 256 + uv4]);
            *reinterpret_cast<float4*>(&t[kk][o][uv4]) = v;
        }
        __syncthreads();
        const int oj = tid & 15, uvg = tid >> 4;
#pragma unroll
        for (int uvp = 0; uvp < 16; uvp++) {
            const int uv = uvp * 16 + uvg;
            g_W2[(((long)s * 256 + uv) * 64 + k2) * 128 + oc * 16 + oj] =
                __floats2half2_rn(4096.0f * t[0][oj][uv],
                                  4096.0f * t[1][oj][uv]);
        }
        __syncthreads();
    }
}

// ---------------------------------------------------------------------------
// K3: fused GEMM + IDWT. grid (17 gy, 32 xr), block 512 (16 warps:
// 8 o-groups x 2 m-groups). dyn smem: sAp uint4[4096] = 64 KB.
// ---------------------------------------------------------------------------
#define KF_SMEM (4096 * 16)

__device__ __forceinline__ void mma_f16(float acc[4], const uint32_t a[4],
                                        const uint32_t b[2]) {
    asm volatile(
        "mma.sync.aligned.m16n8k16.row.col.f32.f16.f16.f32 "
        "{%0,%1,%2,%3}, {%4,%5,%6,%7}, {%8,%9}, {%0,%1,%2,%3};\n"
        : "+f"(acc[0]), "+f"(acc[1]), "+f"(acc[2]), "+f"(acc[3])
        : "r"(a[0]), "r"(a[1]), "r"(a[2]), "r"(a[3]), "r"(b[0]), "r"(b[1]));
}

__device__ __forceinline__ void group_meta(int g, int& start, int& np,
                                           int& t0, float c[2][2]) {
    if (g == 0)       { start = 0;  np = 1; t0 = 0;
                        c[0][0] = 1.0f;  c[0][1] = 0.0f; c[1][0] = 0.0f; c[1][1] = 0.0f; }
    else if (g == 16) { start = 31; np = 1; t0 = 15;
                        c[0][0] = 1.0f;  c[0][1] = 0.0f; c[1][0] = 0.0f; c[1][1] = 0.0f; }
    else              { start = 2 * g - 1; np = 2; t0 = g - 1;
                        c[0][0] = 0.75f; c[0][1] = 0.25f;
                        c[1][0] = 0.25f; c[1][1] = 0.75f; }
}

__device__ __forceinline__ void taps_x(int j, int& i0, int& i1,
                                       float& c0, float& c1) {
    if (j == 0)        { i0 = 0;  i1 = 0;  c0 = 1.0f;  c1 = 0.0f; }
    else if (j == 31)  { i0 = 15; i1 = 15; c0 = 1.0f;  c1 = 0.0f; }
    else if (j & 1)    { int k = j >> 1; i0 = k;     i1 = k + 1; c0 = 0.75f; c1 = 0.25f; }
    else               { int k = j >> 1; i0 = k - 1; i1 = k;     c0 = 0.25f; c1 = 0.75f; }
}

__global__ __launch_bounds__(512, 1) void k_fused(float* __restrict__ out) {
    extern __shared__ uint4 sAp[];   // id = s*1024 + p*512 + kc*64 + m*32 + lane

    const int gy = blockIdx.x, xr = blockIdx.y;
    const int tid = threadIdx.x;

    // y-pair meta (positions, v-taps) and x taps
    int ys, npy, v0t; float cvy[2][2];
    group_meta(gy, ys, npy, v0t, cvy);
    int ux0, ux1; float cx0, cx1;
    taps_x(xr, ux0, ux1, cx0, cx1);

    __half2 cvh[2][2];
#pragma unroll
    for (int p = 0; p < 2; p++)
#pragma unroll
        for (int j = 0; j < 2; j++)
            cvh[p][j] = __half2half2(__float2half_rn(cvy[p][j]));
    const __half2 cxh0 = __half2half2(__float2half_rn(cx0));
    const __half2 cxh1 = __half2half2(__float2half_rn(cx1));

    int posi[2];
    posi[0] = xr * 32 + ys;
    posi[1] = xr * 32 + ys + (npy > 1 ? 1 : 0);

    int uvoff[4];
#pragma unroll
    for (int iu = 0; iu < 2; iu++)
#pragma unroll
        for (int iv = 0; iv < 2; iv++) {
            const int uu = iu ? ux1 : ux0;
            const int vv = v0t + (iv < npy ? iv : 0);
            uvoff[iu * 2 + iv] = uu * 16 + vv;
        }

    // ---- prologue: pack A fragments for all 4 s, both positions ----
#pragma unroll
    for (int j = 0; j < 8; j++) {
        const int id = j * 512 + tid;            // 0..4095
        const int s = id >> 10, rem = id & 1023;
        const int p = rem >> 9, r2 = rem & 511;
        const int kc = r2 >> 6, m2 = (r2 >> 5) & 1, ln = r2 & 31;
        const int gg = ln >> 2, qq = ln & 3;
        const uint32_t* Ab = reinterpret_cast<const uint32_t*>(
            g_A2 + ((long)s * 1024 + posi[p]) * 2048);
        const int r0 = (kc * 8 + qq) * 32 + m2 * 16 + gg;
        uint4 v;
        v.x = __ldg(Ab + r0);
        v.y = __ldg(Ab + r0 + 8);
        v.z = __ldg(Ab + r0 + 128);
        v.w = __ldg(Ab + r0 + 136);
        sAp[id] = v;
    }
    __syncthreads();

    const int warp = tid >> 5, lane = tid & 31;
    const int g = lane >> 2, q = lane & 3;
    const int ow = (warp & 7) << 4;          // 16 o-cols
    const int mw = warp >> 3;                // m-half (batch 16 rows)

    float acc[4][2][2][4];                   // [s][p][n][4]
#pragma unroll
    for (int s = 0; s < 4; s++)
#pragma unroll
        for (int p = 0; p < 2; p++)
#pragma unroll
            for (int n = 0; n < 2; n++)
#pragma unroll
                for (int i = 0; i < 4; i++) acc[s][p][n][i] = 0.0f;

    int jb[4];
#pragma unroll
    for (int j = 0; j < 4; j++)
        jb[j] = uvoff[j] * 8192 + q * 128 + ow + g;

    auto pref = [&](int s, int kc, uint32_t* t) {
        const uint32_t* bs = reinterpret_cast<const uint32_t*>(g_W2)
                           + (long)s * 2097152 + kc * 1024;
#pragma unroll
        for (int n = 0; n < 2; n++)
#pragma unroll
            for (int reg = 0; reg < 2; reg++) {
                const int off = reg * 512 + n * 8;
                const int base = (n * 2 + reg) * 4;
                t[base + 0] = __ldg(bs + jb[0] + off);
                t[base + 1] = __ldg(bs + jb[1] + off);
                t[base + 2] = __ldg(bs + jb[2] + off);
                t[base + 3] = __ldg(bs + jb[3] + off);
            }
    };

    auto compute = [&](int s, const uint32_t* t, int kc) {
#pragma unroll
        for (int n = 0; n < 2; n++) {
            uint32_t bf[2][2];   // [p][reg]
#pragma unroll
            for (int reg = 0; reg < 2; reg++) {
                const int base = (n * 2 + reg) * 4;
                const __half2 t00 = *reinterpret_cast<const __half2*>(&t[base + 0]);
                const __half2 t01 = *reinterpret_cast<const __half2*>(&t[base + 1]);
                const __half2 t10 = *reinterpret_cast<const __half2*>(&t[base + 2]);
                const __half2 t11 = *reinterpret_cast<const __half2*>(&t[base + 3]);
#pragma unroll
                for (int p = 0; p < 2; p++) {
                    const __half2 m0 = __hfma2(cvh[p][0], t00,
                                               __hmul2(cvh[p][1], t01));
                    const __half2 m1 = __hfma2(cvh[p][0], t10,
                                               __hmul2(cvh[p][1], t11));
                    const __half2 r = __hfma2(cxh0, m0, __hmul2(cxh1, m1));
                    bf[p][reg] = *reinterpret_cast<const uint32_t*>(&r);
                }
            }
#pragma unroll
            for (int p = 0; p < 2; p++) {
                const uint4 a = sAp[s * 1024 + p * 512 + kc * 64 + mw * 32 + lane];
                const uint32_t af[4] = {a.x, a.y, a.z, a.w};
                const uint32_t bb[2] = {bf[p][0], bf[p][1]};
                mma_f16(acc[s][p][n], af, bb);
            }
        }
    };

    // ---- barrier-free mainloop: s unrolled (compile-time), kc runtime ----
    uint32_t tA[16], tB[16];
    pref(0, 0, tA);
#pragma unroll
    for (int s = 0; s < 4; s++) {
#pragma unroll 1
        for (int kc = 0; kc < 8; kc += 2) {
            pref(s, kc + 1, tB);
            compute(s, tA, kc);
            if (kc + 2 < 8)      pref(s, kc + 2, tA);
            else if (s < 3)      pref(s + 1, 0, tA);
            compute(s, tB, kc + 1);
        }
    }

    // ---- fused 2-level IDWT epilogue, direct stores ----
    const float SC = 0.25f / 4096.0f;
#pragma unroll
    for (int n = 0; n < 2; n++)
#pragma unroll
        for (int i = 0; i < 4; i++) {
            const int brow = mw * 16 + g + ((i >> 1) << 3);   // batch
            const int o = ow + n * 8 + q * 2 + (i & 1);       // out channel
            float* pb = out + (((long)(brow * 128 + o)) * 128 + 4 * xr) * 128
                      + 4 * ys;
#pragma unroll
            for (int p = 0; p < 2; p++) {
                if (p >= npy) break;
                const float ll = acc[0][p][n][i], lh = acc[1][p][n][i];
                const float hl = acc[2][p][n][i], hh = acc[3][p][n][i];
                const float e00 = SC * (ll + lh + hl + hh);
                const float e01 = SC * (ll - lh + hl - hh);
                const float e10 = SC * (ll + lh - hl - hh);
                const float e11 = SC * (ll - lh - hl + hh);
                const float4 top = make_float4(e00, e00, e01, e01);
                const float4 bot = make_float4(e10, e10, e11, e11);
                float* pp = pb + 4 * p;
                *reinterpret_cast<float4*>(pp)       = top;
                *reinterpret_cast<float4*>(pp + 128) = top;
                *reinterpret_cast<float4*>(pp + 256) = bot;
                *reinterpret_cast<float4*>(pp + 384) = bot;
            }
        }
}

// ---------------------------------------------------------------------------
extern "C" void kernel_launch(void* const* d_in, const int* in_sizes, int n_in,
                              void* d_out, int out_size) {
    (void)in_sizes; (void)n_in; (void)out_size;
    const float* x  = (const float*)d_in[0];
    const float* w1 = (const float*)d_in[1];
    const float* w2 = (const float*)d_in[2];
    const float* w3 = (const float*)d_in[3];
    const float* w4 = (const float*)d_in[4];

    cudaFuncSetAttribute(k_fused, cudaFuncAttributeMaxDynamicSharedMemorySize,
                         KF_SMEM);

    k_dwt  <<<dim3(32, 64), 1024>>>(x);
    k_wprep<<<dim3(64, 4), 256>>>(w1, w2, w3, w4);
    k_fused<<<dim3(17, 32), 512, KF_SMEM>>>((float*)d_out);
}